// round 1
// baseline (speedup 1.0000x reference)
#include <cuda_runtime.h>
#include <cuda_bf16.h>

#define BB 8
#define CC 64
#define CQ 8
#define NN 4096
#define NT 64          // key tile size
#define QT 256         // queries per block / threads per block

// Scratch for projected Q, K, V (device globals: allocation-free rule)
__device__ float g_Q[BB * NN * CQ];   // [b][n][cq]  (1 MB)
__device__ float g_K[BB * NN * CQ];   // [b][n][cq]  (1 MB)
__device__ float g_V[BB * NN * CC];   // [b][n][c]   (8 MB)

// ---------------------------------------------------------------------------
// Kernel 1: 1x1-conv projections (per-pixel linear over channels)
// grid (N/256, B), 256 threads. Each thread = one pixel.
// ---------------------------------------------------------------------------
__global__ void __launch_bounds__(256, 1) proj_kernel(
    const float* __restrict__ x,
    const float* __restrict__ wq, const float* __restrict__ bq,
    const float* __restrict__ wk, const float* __restrict__ bk,
    const float* __restrict__ wv, const float* __restrict__ bv)
{
    __shared__ float wvT[CC * CC];   // wvT[c'][c] = wv[c][c']  (16 KB)
    __shared__ float wqT[CC * CQ];   // wqT[c'][cq]
    __shared__ float wkT[CC * CQ];
    __shared__ float s_bv[CC];
    __shared__ float s_bq[CQ];
    __shared__ float s_bk[CQ];

    const int tid = threadIdx.x;
    const int b   = blockIdx.y;
    const int n   = blockIdx.x * QT + tid;

    // Stage transposed weights (coalesced reads, one-time strided writes)
    for (int idx = tid; idx < CC * CC; idx += 256) {
        int c = idx >> 6, cp = idx & 63;
        wvT[cp * CC + c] = wv[idx];
    }
    for (int idx = tid; idx < CQ * CC; idx += 256) {
        int cq = idx >> 6, cp = idx & 63;
        wqT[cp * CQ + cq] = wq[idx];
        wkT[cp * CQ + cq] = wk[idx];
    }
    if (tid < CC) s_bv[tid] = bv[tid];
    if (tid < CQ) { s_bq[tid] = bq[tid]; s_bk[tid] = bk[tid]; }
    __syncthreads();

    const float* xb = x + (size_t)b * CC * NN + n;

    float4 accv[CC / 4];
    float accq[CQ], acck[CQ];
    #pragma unroll
    for (int c4 = 0; c4 < CC / 4; ++c4) {
        accv[c4].x = s_bv[c4 * 4 + 0];
        accv[c4].y = s_bv[c4 * 4 + 1];
        accv[c4].z = s_bv[c4 * 4 + 2];
        accv[c4].w = s_bv[c4 * 4 + 3];
    }
    #pragma unroll
    for (int cq = 0; cq < CQ; ++cq) { accq[cq] = s_bq[cq]; acck[cq] = s_bk[cq]; }

    #pragma unroll 2
    for (int cp = 0; cp < CC; ++cp) {
        const float xv = xb[(size_t)cp * NN];             // coalesced LDG
        const float4* wrow = (const float4*)&wvT[cp * CC];
        #pragma unroll
        for (int c4 = 0; c4 < CC / 4; ++c4) {
            float4 w = wrow[c4];                           // broadcast LDS.128
            accv[c4].x += w.x * xv;
            accv[c4].y += w.y * xv;
            accv[c4].z += w.z * xv;
            accv[c4].w += w.w * xv;
        }
        #pragma unroll
        for (int cq = 0; cq < CQ; ++cq) {
            accq[cq] += wqT[cp * CQ + cq] * xv;
            acck[cq] += wkT[cp * CQ + cq] * xv;
        }
    }

    // Store: Q/K [b][n][8], V [b][n][64] (16B-aligned vector stores)
    float4* Qo = (float4*)(g_Q + ((size_t)b * NN + n) * CQ);
    float4* Ko = (float4*)(g_K + ((size_t)b * NN + n) * CQ);
    Qo[0] = make_float4(accq[0], accq[1], accq[2], accq[3]);
    Qo[1] = make_float4(accq[4], accq[5], accq[6], accq[7]);
    Ko[0] = make_float4(acck[0], acck[1], acck[2], acck[3]);
    Ko[1] = make_float4(acck[4], acck[5], acck[6], acck[7]);

    float4* Vo = (float4*)(g_V + ((size_t)b * NN + n) * CC);
    #pragma unroll
    for (int c4 = 0; c4 < CC / 4; ++c4) Vo[c4] = accv[c4];
}

// ---------------------------------------------------------------------------
// Kernel 2: fused flash attention. One query per thread, 256 queries/block.
// grid (N/256, B) = (16, 8) = 128 blocks, single wave.
// Dynamic smem: K tile (512 f) | V tile (4096 f) | S tile (64*256 f) = 84 KB
// ---------------------------------------------------------------------------
#define SMEM_K_OFF  0
#define SMEM_V_OFF  512
#define SMEM_S_OFF  (512 + 4096)
#define SMEM_FLOATS (512 + 4096 + NT * QT)

__global__ void __launch_bounds__(256, 1) attn_kernel(float* __restrict__ out)
{
    extern __shared__ __align__(16) float sm[];
    float4* Ks   = (float4*)(sm + SMEM_K_OFF);   // [64 keys][2 float4]
    float4* Vs   = (float4*)(sm + SMEM_V_OFF);   // [64 keys][16 float4]
    float*  Ssm  = sm + SMEM_S_OFF;              // [j][tid]

    const int tid = threadIdx.x;
    const int b   = blockIdx.y;
    const int i   = blockIdx.x * QT + tid;

    const float4* Qp = (const float4*)(g_Q + ((size_t)b * NN + i) * CQ);
    const float4 q0 = Qp[0];
    const float4 q1 = Qp[1];

    const float4* Kg4 = (const float4*)(g_K + (size_t)b * NN * CQ);
    const float4* Vg4 = (const float4*)(g_V + (size_t)b * NN * CC);

    float4 o[CC / 4];
    #pragma unroll
    for (int c4 = 0; c4 < CC / 4; ++c4) o[c4] = make_float4(0.f, 0.f, 0.f, 0.f);
    float m = -1e30f;
    float l = 0.f;

    #pragma unroll 1
    for (int t = 0; t < NN / NT; ++t) {
        __syncthreads();
        if (tid < 128) Ks[tid] = Kg4[t * 128 + tid];
        #pragma unroll
        for (int r = 0; r < 4; ++r) Vs[r * 256 + tid] = Vg4[t * 1024 + r * 256 + tid];
        __syncthreads();

        // --- scores + tile max (S staged in smem, conflict-free [j][tid]) ---
        float tmax = -1e30f;
        #pragma unroll 8
        for (int j = 0; j < NT; ++j) {
            float4 k0 = Ks[j * 2 + 0];                    // broadcast
            float4 k1 = Ks[j * 2 + 1];
            float s = q0.x * k0.x + q0.y * k0.y + q0.z * k0.z + q0.w * k0.w
                    + q1.x * k1.x + q1.y * k1.y + q1.z * k1.z + q1.w * k1.w;
            Ssm[j * QT + tid] = s;
            tmax = fmaxf(tmax, s);
        }

        // --- online softmax rescale (thread-private state) ---
        const float newm  = fmaxf(m, tmax);
        const float scale = __expf(m - newm);
        m = newm;
        l *= scale;
        #pragma unroll
        for (int c4 = 0; c4 < CC / 4; ++c4) {
            o[c4].x *= scale; o[c4].y *= scale; o[c4].z *= scale; o[c4].w *= scale;
        }

        // --- P @ V accumulate ---
        #pragma unroll 4
        for (int j = 0; j < NT; ++j) {
            const float p = __expf(Ssm[j * QT + tid] - m);
            l += p;
            const float4* vrow = &Vs[j * 16];
            #pragma unroll
            for (int c4 = 0; c4 < CC / 4; ++c4) {
                float4 v = vrow[c4];                      // broadcast
                o[c4].x += p * v.x;
                o[c4].y += p * v.y;
                o[c4].z += p * v.z;
                o[c4].w += p * v.w;
            }
        }
    }

    const float inv = 1.0f / l;
    float* op = out + (size_t)b * CC * NN + i;            // out[b][c][i]
    #pragma unroll
    for (int c4 = 0; c4 < CC / 4; ++c4) {
        op[(size_t)(c4 * 4 + 0) * NN] = o[c4].x * inv;
        op[(size_t)(c4 * 4 + 1) * NN] = o[c4].y * inv;
        op[(size_t)(c4 * 4 + 2) * NN] = o[c4].z * inv;
        op[(size_t)(c4 * 4 + 3) * NN] = o[c4].w * inv;
    }
}

// ---------------------------------------------------------------------------
extern "C" void kernel_launch(void* const* d_in, const int* in_sizes, int n_in,
                              void* d_out, int out_size)
{
    const float* x  = (const float*)d_in[0];
    const float* wq = (const float*)d_in[1];
    const float* bq = (const float*)d_in[2];
    const float* wk = (const float*)d_in[3];
    const float* bk = (const float*)d_in[4];
    const float* wv = (const float*)d_in[5];
    const float* bv = (const float*)d_in[6];
    float* out = (float*)d_out;

    cudaFuncSetAttribute(attn_kernel, cudaFuncAttributeMaxDynamicSharedMemorySize,
                         SMEM_FLOATS * (int)sizeof(float));

    dim3 grid(NN / QT, BB);
    proj_kernel<<<grid, 256>>>(x, wq, bq, wk, bk, wv, bv);
    attn_kernel<<<grid, 256, SMEM_FLOATS * sizeof(float)>>>(out);
}